// round 12
// baseline (speedup 1.0000x reference)
#include <cuda_runtime.h>
#include <cstdint>

// Inputs (metadata order):
//   d_in[0] state           float32 [B, A, N, 3]
//   d_in[1] nodes_coords    float32 [P, 2]
//   d_in[2] adj             float32 [P, N]
//   d_in[3] node_last_visit int32   [B, A]
//   d_in[4] patrol_index    int32   [P]
// Output: float32 [B, A, N, 6]
//
// Persistent kernel: 16 CTAs/SM, each CTA loops over rows with double-buffered
// smem. Each WARP is an independent pipeline: gather row -> STS.128 into
// buf[parity] -> commit per-warp bulk store -> wait_group.read 1 (previous
// row's store drains behind this row's gather). No __syncthreads anywhere.

__global__ __launch_bounds__(128)
void policy_gather_kernel(const float* __restrict__ state,
                          const float* __restrict__ coords,
                          const float* __restrict__ adj,
                          const int*   __restrict__ nlv,
                          const int*   __restrict__ pidx,
                          float* __restrict__ out,
                          int N, int BA) {
    extern __shared__ __align__(16) float s_tiles[];   // 2 * N*6 floats

    const int t     = threadIdx.x;
    const int warp  = t >> 5;
    const int lane  = t & 31;
    const int tileN = N * 6;
    const int pairs = N >> 1;

    const bool okA   = ((((uintptr_t)state) | ((uintptr_t)adj)) & 7) == 0;
    const bool okTMA = ((((uintptr_t)out) & 0xF) == 0);
    // One bulk chunk per warp per row iff pairs <= 128 (true for N <= 257).
    const bool oneChunk = (pairs <= 128);

    if (okA && okTMA && oneChunk) {
        int parity = 0;
        for (int row = blockIdx.x; row < BA; row += gridDim.x) {
            float* s_buf = s_tiles + parity * tileN;

            // Row-constant chain (hidden by cross-warp/CTA concurrency).
            const int   v   = __ldg(nlv + row);
            const int   idx = __ldg(pidx + v);
            const float zx  = __ldg(coords + 2 * v);
            const float zy  = __ldg(coords + 2 * v + 1);

            const float* __restrict__ st = state + (size_t)row * N * 3;  // 8B aligned
            const float* __restrict__ ar = adj   + (size_t)idx * N;      // 8B aligned
            float* __restrict__ orow     = out   + (size_t)row * tileN;  // 16B aligned

            const int start = warp * 32;
            const int cnt   = min(32, pairs - start);   // may be <=0 only if pairs<97
            const int p     = start + lane;

            if (lane < cnt) {
                const float2 s01 = __ldcs(reinterpret_cast<const float2*>(st + 6 * p));
                const float2 s23 = __ldcs(reinterpret_cast<const float2*>(st + 6 * p + 2));
                const float2 s45 = __ldcs(reinterpret_cast<const float2*>(st + 6 * p + 4));
                const float2 aa  = __ldg (reinterpret_cast<const float2*>(ar + 2 * p));

                float4* d = reinterpret_cast<float4*>(s_buf + 12 * p);   // 16B aligned
                d[0] = make_float4(s01.x, s01.y, s23.x, zx);
                d[1] = make_float4(zy,    aa.x,  s23.y, s45.x);
                d[2] = make_float4(s45.y, zx,    zy,    aa.y);
            }
            __syncwarp();
            asm volatile("fence.proxy.async.shared::cta;" ::: "memory");

            if (cnt > 0 && lane == 0) {
                const unsigned bytes = (unsigned)(cnt * 12 * sizeof(float));  // mult of 48
                float* gdst = orow + (size_t)start * 12;
                uint32_t saddr;
                asm("{ .reg .u64 tmp; cvta.to.shared.u64 tmp, %1; cvt.u32.u64 %0, tmp; }"
                    : "=r"(saddr) : "l"(s_buf + 12 * start));
                asm volatile(
                    "cp.async.bulk.global.shared::cta.bulk_group [%0], [%1], %2;"
                    :: "l"(gdst), "r"(saddr), "r"(bytes) : "memory");
                asm volatile("cp.async.bulk.commit_group;" ::: "memory");
                // Keep one group in flight: the PREVIOUS row's store must have
                // finished reading its buffer before we reuse it next iteration.
                asm volatile("cp.async.bulk.wait_group.read 1;" ::: "memory");
            }

            // Odd-N tail node: direct scalar stores (no smem, no ordering issue).
            if ((N & 1) && t == 0) {
                const int n = N - 1;
                float* d = orow + 6 * n;
                __stcs(d + 0, st[3 * n + 0]);
                __stcs(d + 1, st[3 * n + 1]);
                __stcs(d + 2, st[3 * n + 2]);
                __stcs(d + 3, zx);
                __stcs(d + 4, zy);
                __stcs(d + 5, ar[n]);
            }

            parity ^= 1;
        }
        // Final drain: smem READ completion only.
        if (lane == 0) {
            asm volatile("cp.async.bulk.wait_group.read 0;" ::: "memory");
        }
    } else {
        // Fallback: staged scalar copy per row with full-block sync.
        for (int row = blockIdx.x; row < BA; row += gridDim.x) {
            const int   v   = __ldg(nlv + row);
            const int   idx = __ldg(pidx + v);
            const float zx  = __ldg(coords + 2 * v);
            const float zy  = __ldg(coords + 2 * v + 1);
            const float* __restrict__ st = state + (size_t)row * N * 3;
            const float* __restrict__ ar = adj   + (size_t)idx * N;
            float* __restrict__ orow     = out   + (size_t)row * tileN;
            for (int n = t; n < N; n += blockDim.x) {
                float* d = orow + 6 * n;
                d[0] = st[3 * n + 0];
                d[1] = st[3 * n + 1];
                d[2] = st[3 * n + 2];
                d[3] = zx;
                d[4] = zy;
                d[5] = ar[n];
            }
        }
    }
}

extern "C" void kernel_launch(void* const* d_in, const int* in_sizes, int n_in,
                              void* d_out, int out_size) {
    const float* state  = (const float*)d_in[0];
    const float* coords = (const float*)d_in[1];
    const float* adj    = (const float*)d_in[2];
    const int*   nlv    = (const int*)d_in[3];
    const int*   pidx   = (const int*)d_in[4];
    float*       out    = (float*)d_out;

    const int BA = in_sizes[3];            // B * A rows
    const int P  = in_sizes[4];            // patrol nodes
    const int N  = in_sizes[2] / P;        // graph size (adj is [P, N])

    // Persistent grid: 16 CTAs/SM on 152 SMs (GB300); clamp to row count.
    int grid = 152 * 16;
    if (grid > BA) grid = BA;

    const size_t smem = (size_t)2 * N * 6 * sizeof(float);
    policy_gather_kernel<<<grid, 128, smem>>>(state, coords, adj, nlv, pidx, out, N, BA);
}

// round 13
// speedup vs baseline: 1.1969x; 1.1969x over previous
#include <cuda_runtime.h>
#include <cstdint>

// Inputs (metadata order):
//   d_in[0] state           float32 [B, A, N, 3]
//   d_in[1] nodes_coords    float32 [P, 2]
//   d_in[2] adj             float32 [P, N]
//   d_in[3] node_last_visit int32   [B, A]
//   d_in[4] patrol_index    int32   [P]
// Output: float32 [B, A, N, 6]
//
// R10 structure (best: per-warp independent gather -> STS.128 -> per-warp TMA
// bulk store, no __syncthreads) + latency micro-opts:
//   * state LDGs issued before the nlv->pidx->coords chain (overlap DRAM
//     latency with the chain instead of queueing behind it)
//   * speculative per-lane L1 prefetch of the adj row using v (pidx is
//     identity in this dataset; prefetch is correct-by-construction either way)

__global__ __launch_bounds__(128)
void policy_gather_kernel(const float* __restrict__ state,
                          const float* __restrict__ coords,
                          const float* __restrict__ adj,
                          const int*   __restrict__ nlv,
                          const int*   __restrict__ pidx,
                          float* __restrict__ out,
                          int N) {
    extern __shared__ __align__(16) float s_row[];   // N*6 floats, output-row image

    const int row  = blockIdx.x;
    const int t    = threadIdx.x;
    const int warp = t >> 5;
    const int lane = t & 31;

    const float* __restrict__ st = state + (size_t)row * N * 3;   // 8B aligned
    float* __restrict__ orow     = out   + (size_t)row * N * 6;   // 16B aligned

    const bool okA   = ((((uintptr_t)st) & 7) == 0) && ((((uintptr_t)adj) & 7) == 0);
    const bool okTMA = ((((uintptr_t)orow) & 0xF) == 0);
    const int pairs  = N >> 1;

    if (okA && okTMA && pairs <= 128) {
        const int start = warp * 32;
        const int cnt   = pairs - start;            // lanes < cnt are active
        const int p     = start + lane;
        const bool act  = (lane < cnt);

        // (1) Independent state loads FIRST: their DRAM latency overlaps the
        //     row-constant chain below.
        float2 s01 = make_float2(0.f, 0.f), s23 = s01, s45 = s01;
        if (act) {
            s01 = __ldcs(reinterpret_cast<const float2*>(st + 6 * p));
            s23 = __ldcs(reinterpret_cast<const float2*>(st + 6 * p + 2));
            s45 = __ldcs(reinterpret_cast<const float2*>(st + 6 * p + 4));
        }

        // (2) Row-constant chain, with speculative adj prefetch off v.
        const int v = __ldg(nlv + row);
        if (act) {
            const float* pf = adj + (size_t)v * N + 2 * p;
            asm volatile("prefetch.global.L1 [%0];" :: "l"(pf));
        }
        const int   idx = __ldg(pidx + v);
        const float zx  = __ldg(coords + 2 * v);
        const float zy  = __ldg(coords + 2 * v + 1);

        const float* __restrict__ ar = adj + (size_t)idx * N;      // 8B aligned

        if (act) {
            const float2 aa = __ldg(reinterpret_cast<const float2*>(ar + 2 * p));

            float4* d = reinterpret_cast<float4*>(s_row + 12 * p); // 16B aligned
            d[0] = make_float4(s01.x, s01.y, s23.x, zx);
            d[1] = make_float4(zy,    aa.x,  s23.y, s45.x);
            d[2] = make_float4(s45.y, zx,    zy,    aa.y);
        }
        __syncwarp();
        asm volatile("fence.proxy.async.shared::cta;" ::: "memory");

        if (cnt > 0 && lane == 0) {
            const int c = min(32, cnt);
            const unsigned bytes = (unsigned)(c * 12 * sizeof(float));  // mult of 48
            float* gdst = orow + (size_t)start * 12;
            uint32_t saddr;
            asm("{ .reg .u64 tmp; cvta.to.shared.u64 tmp, %1; cvt.u32.u64 %0, tmp; }"
                : "=r"(saddr) : "l"(s_row + 12 * start));
            asm volatile(
                "cp.async.bulk.global.shared::cta.bulk_group [%0], [%1], %2;"
                :: "l"(gdst), "r"(saddr), "r"(bytes) : "memory");
            asm volatile("cp.async.bulk.commit_group;" ::: "memory");
        }

        // Odd-N tail node.
        if ((N & 1) && t == 0) {
            const int n = N - 1;
            float* dsc = orow + 6 * n;
            __stcs(dsc + 0, st[3 * n + 0]);
            __stcs(dsc + 1, st[3 * n + 1]);
            __stcs(dsc + 2, st[3 * n + 2]);
            __stcs(dsc + 3, zx);
            __stcs(dsc + 4, zy);
            __stcs(dsc + 5, ar[n]);
        }

        // Exit gate: smem READ completion only.
        if (lane == 0) {
            asm volatile("cp.async.bulk.wait_group.read 0;" ::: "memory");
        }
    } else {
        // Fallback: staged scalar copy with full-block sync.
        const int v   = __ldg(nlv + row);
        const int idx = __ldg(pidx + v);
        const float zx = __ldg(coords + 2 * v);
        const float zy = __ldg(coords + 2 * v + 1);
        const float* __restrict__ ar = adj + (size_t)idx * N;
        for (int n = t; n < N; n += blockDim.x) {
            float* d = s_row + 6 * n;
            d[0] = st[3 * n + 0];
            d[1] = st[3 * n + 1];
            d[2] = st[3 * n + 2];
            d[3] = zx;
            d[4] = zy;
            d[5] = ar[n];
        }
        __syncthreads();
        const int total = N * 6;
        for (int j = t; j < total; j += blockDim.x) {
            __stcs(orow + j, s_row[j]);
        }
    }
}

extern "C" void kernel_launch(void* const* d_in, const int* in_sizes, int n_in,
                              void* d_out, int out_size) {
    const float* state  = (const float*)d_in[0];
    const float* coords = (const float*)d_in[1];
    const float* adj    = (const float*)d_in[2];
    const int*   nlv    = (const int*)d_in[3];
    const int*   pidx   = (const int*)d_in[4];
    float*       out    = (float*)d_out;

    const int BA = in_sizes[3];            // B * A rows
    const int P  = in_sizes[4];            // patrol nodes
    const int N  = in_sizes[2] / P;        // graph size (adj is [P, N])

    const size_t smem = (size_t)N * 6 * sizeof(float);
    policy_gather_kernel<<<BA, 128, smem>>>(state, coords, adj, nlv, pidx, out, N);
}